// round 1
// baseline (speedup 1.0000x reference)
#include <cuda_runtime.h>
#include <math.h>
#include <float.h>

#define NMAX 100000
#define DD 512
#define QD 128
#define BBLK 64

// ---------------- scratch (static __device__, no allocations) ----------------
static __device__ float g_predsmod[NMAX];
static __device__ float g_scale[NMAX];
static __device__ float g_f[(size_t)NMAX * DD];
static __device__ float g_V[(size_t)NMAX * DD];
static __device__ float g_Alog[(size_t)NMAX * 2];

static __device__ unsigned g_hist[256];
static __device__ unsigned g_prefix;
static __device__ int g_krem;
static __device__ unsigned g_thresh;

static __device__ float g_pmax[256];
static __device__ float g_maxv;
static __device__ float g_psum[256];
static __device__ float g_sumv;

static __device__ float g_cpv[128 * 2];
static __device__ int g_cpi[128 * 2];
static __device__ int g_midx[2];
static __device__ float g_qmax[2 * QD];

static __device__ float g_apm[256 * 2];
static __device__ float g_amax[2];
static __device__ float g_aps[256 * 2];
static __device__ float g_asum[2];

static __device__ float g_Bpart[BBLK * 2 * DD];
static __device__ float g_B[2 * DD];

// order-preserving float -> uint key (ascending)
static __device__ __forceinline__ unsigned f2key(float x) {
    unsigned u = __float_as_uint(x);
    return (u & 0x80000000u) ? ~u : (u | 0x80000000u);
}

// ---------------- radix select (k-th smallest) ----------------
__global__ void init_sel(int k) {
    g_hist[threadIdx.x] = 0u;
    if (threadIdx.x == 0) { g_prefix = 0u; g_krem = k; }
}

__global__ void hist_kernel(const float* __restrict__ preds, int n, int p) {
    __shared__ unsigned sh[256];
    sh[threadIdx.x] = 0u;
    __syncthreads();
    int shift = 24 - 8 * p;
    unsigned pref = g_prefix;
    for (int i = blockIdx.x * blockDim.x + threadIdx.x; i < n; i += gridDim.x * blockDim.x) {
        unsigned key = f2key(preds[i]);
        bool m = (p == 0) || ((key >> (shift + 8)) == pref);
        if (m) atomicAdd(&sh[(key >> shift) & 255u], 1u);
    }
    __syncthreads();
    if (sh[threadIdx.x]) atomicAdd(&g_hist[threadIdx.x], sh[threadIdx.x]);
}

__global__ void scan_kernel(int p) {
    if (threadIdx.x == 0) {
        int krem = g_krem;
        unsigned cum = 0;
        int b = 0;
        for (b = 0; b < 256; b++) {
            unsigned h = g_hist[b];
            if (cum + h >= (unsigned)krem) break;
            cum += h;
        }
        g_prefix = (g_prefix << 8) | (unsigned)b;
        g_krem = krem - (int)cum;
        if (p == 3) g_thresh = g_prefix;
    }
    __syncthreads();
    g_hist[threadIdx.x] = 0u;
}

__global__ void zero_kernel(const float* __restrict__ preds, int n) {
    unsigned th = g_thresh;
    for (int i = blockIdx.x * blockDim.x + threadIdx.x; i < n; i += gridDim.x * blockDim.x) {
        float v = preds[i];
        g_predsmod[i] = (f2key(v) <= th) ? 0.0f : v;
    }
}

// ---------------- softmax(preds) -> scale = 1 + softmax ----------------
__global__ void maxpart(int n) {
    __shared__ float sm[256];
    float m = -FLT_MAX;
    for (int i = blockIdx.x * blockDim.x + threadIdx.x; i < n; i += gridDim.x * blockDim.x)
        m = fmaxf(m, g_predsmod[i]);
    sm[threadIdx.x] = m;
    __syncthreads();
    for (int st = 128; st; st >>= 1) {
        if (threadIdx.x < st) sm[threadIdx.x] = fmaxf(sm[threadIdx.x], sm[threadIdx.x + st]);
        __syncthreads();
    }
    if (threadIdx.x == 0) g_pmax[blockIdx.x] = sm[0];
}

__global__ void maxfin() {
    __shared__ float sm[256];
    sm[threadIdx.x] = g_pmax[threadIdx.x];
    __syncthreads();
    for (int st = 128; st; st >>= 1) {
        if (threadIdx.x < st) sm[threadIdx.x] = fmaxf(sm[threadIdx.x], sm[threadIdx.x + st]);
        __syncthreads();
    }
    if (threadIdx.x == 0) g_maxv = sm[0];
}

__global__ void sumpart(int n) {
    __shared__ float sm[256];
    float mx = g_maxv;
    float s = 0.f;
    for (int i = blockIdx.x * blockDim.x + threadIdx.x; i < n; i += gridDim.x * blockDim.x)
        s += expf(g_predsmod[i] - mx);
    sm[threadIdx.x] = s;
    __syncthreads();
    for (int st = 128; st; st >>= 1) {
        if (threadIdx.x < st) sm[threadIdx.x] += sm[threadIdx.x + st];
        __syncthreads();
    }
    if (threadIdx.x == 0) g_psum[blockIdx.x] = sm[0];
}

__global__ void sumfin() {
    __shared__ float sm[256];
    sm[threadIdx.x] = g_psum[threadIdx.x];
    __syncthreads();
    for (int st = 128; st; st >>= 1) {
        if (threadIdx.x < st) sm[threadIdx.x] += sm[threadIdx.x + st];
        __syncthreads();
    }
    if (threadIdx.x == 0) g_sumv = sm[0];
}

__global__ void scalek(int n) {
    float mx = g_maxv, sv = g_sumv;
    for (int i = blockIdx.x * blockDim.x + threadIdx.x; i < n; i += gridDim.x * blockDim.x)
        g_scale[i] = 1.0f + expf(g_predsmod[i] - mx) / sv;
}

// ---------------- 128x128 tiled SGEMM, 8x8 register blocking ----------------
// mode 0: out = relu((feats*scale) @ W^T + bias) -> g_f
// mode 1: out = g_f @ W^T + bias               -> g_V
__global__ void __launch_bounds__(256) gemm_kernel(const float* __restrict__ Aext,
                                                   const float* __restrict__ W,
                                                   const float* __restrict__ bias,
                                                   int n, int mode) {
    __shared__ float As[8][128];
    __shared__ float Ws[8][128];
    const float* A = (mode == 0) ? Aext : g_f;
    float* out = (mode == 0) ? g_f : g_V;
    int tid = threadIdx.x;
    int ty = tid >> 4, tx = tid & 15;
    int rowBase = blockIdx.x * 128;
    int colBase = blockIdx.y * 128;
    float acc[8][8];
#pragma unroll
    for (int i = 0; i < 8; i++)
#pragma unroll
        for (int j = 0; j < 8; j++) acc[i][j] = 0.f;

    int ml = tid >> 1;
    int kq = (tid & 1) * 4;
    int arow = rowBase + ml;
    bool avalid = arow < n;
    float sc = 1.f;
    if (mode == 0 && avalid) sc = g_scale[arow];
    const float* Aptr = A + (avalid ? (size_t)arow * DD : 0);
    const float* Wptr = W + (size_t)(colBase + ml) * DD;

    for (int kt = 0; kt < DD; kt += 8) {
        float4 av = make_float4(0.f, 0.f, 0.f, 0.f);
        if (avalid) av = *(const float4*)(Aptr + kt + kq);
        As[kq + 0][ml] = av.x * sc; As[kq + 1][ml] = av.y * sc;
        As[kq + 2][ml] = av.z * sc; As[kq + 3][ml] = av.w * sc;
        float4 wv = *(const float4*)(Wptr + kt + kq);
        Ws[kq + 0][ml] = wv.x; Ws[kq + 1][ml] = wv.y;
        Ws[kq + 2][ml] = wv.z; Ws[kq + 3][ml] = wv.w;
        __syncthreads();
#pragma unroll
        for (int kk = 0; kk < 8; kk++) {
            float a[8], b[8];
            const float4* Ap = (const float4*)&As[kk][ty * 8];
            const float4* Bp = (const float4*)&Ws[kk][tx * 8];
            float4 a0 = Ap[0], a1 = Ap[1];
            float4 b0 = Bp[0], b1 = Bp[1];
            a[0] = a0.x; a[1] = a0.y; a[2] = a0.z; a[3] = a0.w;
            a[4] = a1.x; a[5] = a1.y; a[6] = a1.z; a[7] = a1.w;
            b[0] = b0.x; b[1] = b0.y; b[2] = b0.z; b[3] = b0.w;
            b[4] = b1.x; b[5] = b1.y; b[6] = b1.z; b[7] = b1.w;
#pragma unroll
            for (int i = 0; i < 8; i++)
#pragma unroll
                for (int j = 0; j < 8; j++) acc[i][j] = fmaf(a[i], b[j], acc[i][j]);
        }
        __syncthreads();
    }
#pragma unroll
    for (int i = 0; i < 8; i++) {
        int r = rowBase + ty * 8 + i;
        if (r >= n) continue;
#pragma unroll
        for (int j = 0; j < 8; j++) {
            int o = colBase + tx * 8 + j;
            float v = acc[i][j] + bias[o];
            if (mode == 0) v = fmaxf(v, 0.f);
            out[(size_t)r * DD + o] = v;
        }
    }
}

// ---------------- argmax over c columns (deterministic 2-stage) ----------------
__global__ void cargpart(const float* __restrict__ c, int n) {
    __shared__ float sv[256][2];
    __shared__ int si[256][2];
    float bv0 = -FLT_MAX, bv1 = -FLT_MAX;
    int bi0 = 0x7fffffff, bi1 = 0x7fffffff;
    for (int i = blockIdx.x * blockDim.x + threadIdx.x; i < n; i += gridDim.x * blockDim.x) {
        float v0 = c[(size_t)i * 2];
        float v1 = c[(size_t)i * 2 + 1];
        if (v0 > bv0 || (v0 == bv0 && i < bi0)) { bv0 = v0; bi0 = i; }
        if (v1 > bv1 || (v1 == bv1 && i < bi1)) { bv1 = v1; bi1 = i; }
    }
    sv[threadIdx.x][0] = bv0; si[threadIdx.x][0] = bi0;
    sv[threadIdx.x][1] = bv1; si[threadIdx.x][1] = bi1;
    __syncthreads();
    for (int st = 128; st; st >>= 1) {
        if (threadIdx.x < st) {
#pragma unroll
            for (int cc = 0; cc < 2; cc++) {
                float v = sv[threadIdx.x + st][cc];
                int ii = si[threadIdx.x + st][cc];
                if (v > sv[threadIdx.x][cc] ||
                    (v == sv[threadIdx.x][cc] && ii < si[threadIdx.x][cc])) {
                    sv[threadIdx.x][cc] = v;
                    si[threadIdx.x][cc] = ii;
                }
            }
        }
        __syncthreads();
    }
    if (threadIdx.x == 0) {
        g_cpv[blockIdx.x * 2 + 0] = sv[0][0]; g_cpi[blockIdx.x * 2 + 0] = si[0][0];
        g_cpv[blockIdx.x * 2 + 1] = sv[0][1]; g_cpi[blockIdx.x * 2 + 1] = si[0][1];
    }
}

__global__ void cargfin() {
    int cc = threadIdx.x;
    if (cc < 2) {
        float bv = -FLT_MAX;
        int bi = 0x7fffffff;
        for (int b = 0; b < 128; b++) {
            float v = g_cpv[b * 2 + cc];
            int ii = g_cpi[b * 2 + cc];
            if (v > bv || (v == bv && ii < bi)) { bv = v; bi = ii; }
        }
        g_midx[cc] = bi;
    }
}

// ---------------- q_max = tanh(f[m_idx] @ W_q^T + b_q) ----------------
__global__ void qmaxk(const float* __restrict__ Wq, const float* __restrict__ bq) {
    int t = threadIdx.x;
    int cls = t >> 7, j = t & 127;
    const float* frow = g_f + (size_t)g_midx[cls] * DD;
    const float* wrow = Wq + (size_t)j * DD;
    float s = 0.f;
    for (int d = 0; d < DD; d++) s = fmaf(frow[d], wrow[d], s);
    g_qmax[cls * QD + j] = tanhf(s + bq[j]);
}

// ---------------- Q GEMM fused with A-logit epilogue ----------------
__global__ void __launch_bounds__(256) gemmq_kernel(const float* __restrict__ Wq,
                                                    const float* __restrict__ bq, int n) {
    __shared__ float As[8][128];
    __shared__ float Ws[8][128];
    __shared__ float pA[2][16][8][16];
    int tid = threadIdx.x;
    int ty = tid >> 4, tx = tid & 15;
    int rowBase = blockIdx.x * 128;
    float acc[8][8];
#pragma unroll
    for (int i = 0; i < 8; i++)
#pragma unroll
        for (int j = 0; j < 8; j++) acc[i][j] = 0.f;

    int ml = tid >> 1;
    int kq = (tid & 1) * 4;
    int arow = rowBase + ml;
    bool avalid = arow < n;
    const float* Aptr = g_f + (avalid ? (size_t)arow * DD : 0);
    const float* Wptr = Wq + (size_t)ml * DD;

    for (int kt = 0; kt < DD; kt += 8) {
        float4 av = make_float4(0.f, 0.f, 0.f, 0.f);
        if (avalid) av = *(const float4*)(Aptr + kt + kq);
        As[kq + 0][ml] = av.x; As[kq + 1][ml] = av.y;
        As[kq + 2][ml] = av.z; As[kq + 3][ml] = av.w;
        float4 wv = *(const float4*)(Wptr + kt + kq);
        Ws[kq + 0][ml] = wv.x; Ws[kq + 1][ml] = wv.y;
        Ws[kq + 2][ml] = wv.z; Ws[kq + 3][ml] = wv.w;
        __syncthreads();
#pragma unroll
        for (int kk = 0; kk < 8; kk++) {
            float a[8], b[8];
            const float4* Ap = (const float4*)&As[kk][ty * 8];
            const float4* Bp = (const float4*)&Ws[kk][tx * 8];
            float4 a0 = Ap[0], a1 = Ap[1];
            float4 b0 = Bp[0], b1 = Bp[1];
            a[0] = a0.x; a[1] = a0.y; a[2] = a0.z; a[3] = a0.w;
            a[4] = a1.x; a[5] = a1.y; a[6] = a1.z; a[7] = a1.w;
            b[0] = b0.x; b[1] = b0.y; b[2] = b0.z; b[3] = b0.w;
            b[4] = b1.x; b[5] = b1.y; b[6] = b1.z; b[7] = b1.w;
#pragma unroll
            for (int i = 0; i < 8; i++)
#pragma unroll
                for (int j = 0; j < 8; j++) acc[i][j] = fmaf(a[i], b[j], acc[i][j]);
        }
        __syncthreads();
    }

    // epilogue: Q = tanh(acc + bq); A_logit[r][c] = (Q . q_max[c]) / sqrt(128)
    float p0[8], p1[8];
#pragma unroll
    for (int i = 0; i < 8; i++) { p0[i] = 0.f; p1[i] = 0.f; }
#pragma unroll
    for (int j = 0; j < 8; j++) {
        int o = tx * 8 + j;
        float qm0 = g_qmax[o];
        float qm1 = g_qmax[QD + o];
        float bqo = bq[o];
#pragma unroll
        for (int i = 0; i < 8; i++) {
            float q = tanhf(acc[i][j] + bqo);
            p0[i] = fmaf(q, qm0, p0[i]);
            p1[i] = fmaf(q, qm1, p1[i]);
        }
    }
#pragma unroll
    for (int i = 0; i < 8; i++) {
        pA[0][ty][i][tx] = p0[i];
        pA[1][ty][i][tx] = p1[i];
    }
    __syncthreads();
    int cc = tid >> 7;
    int rem = tid & 127;
    int tyy = rem >> 3, ii = rem & 7;
    float s = 0.f;
#pragma unroll
    for (int t = 0; t < 16; t++) s += pA[cc][tyy][ii][t];
    int r = rowBase + tyy * 8 + ii;
    if (r < n) g_Alog[(size_t)r * 2 + cc] = s * 0.08838834764831845f; // 1/sqrt(128)
}

// ---------------- column softmax of A-logits ----------------
__global__ void amaxpart(int n) {
    __shared__ float s0[256], s1[256];
    float m0 = -FLT_MAX, m1 = -FLT_MAX;
    for (int i = blockIdx.x * blockDim.x + threadIdx.x; i < n; i += gridDim.x * blockDim.x) {
        m0 = fmaxf(m0, g_Alog[(size_t)i * 2]);
        m1 = fmaxf(m1, g_Alog[(size_t)i * 2 + 1]);
    }
    s0[threadIdx.x] = m0; s1[threadIdx.x] = m1;
    __syncthreads();
    for (int st = 128; st; st >>= 1) {
        if (threadIdx.x < st) {
            s0[threadIdx.x] = fmaxf(s0[threadIdx.x], s0[threadIdx.x + st]);
            s1[threadIdx.x] = fmaxf(s1[threadIdx.x], s1[threadIdx.x + st]);
        }
        __syncthreads();
    }
    if (threadIdx.x == 0) { g_apm[blockIdx.x * 2] = s0[0]; g_apm[blockIdx.x * 2 + 1] = s1[0]; }
}

__global__ void amaxfin() {
    if (threadIdx.x < 2) {
        int cc = threadIdx.x;
        float m = -FLT_MAX;
        for (int b = 0; b < 256; b++) m = fmaxf(m, g_apm[b * 2 + cc]);
        g_amax[cc] = m;
    }
}

__global__ void asumpart(int n) {
    __shared__ float s0[256], s1[256];
    float m0 = g_amax[0], m1 = g_amax[1];
    float a0 = 0.f, a1 = 0.f;
    for (int i = blockIdx.x * blockDim.x + threadIdx.x; i < n; i += gridDim.x * blockDim.x) {
        a0 += expf(g_Alog[(size_t)i * 2] - m0);
        a1 += expf(g_Alog[(size_t)i * 2 + 1] - m1);
    }
    s0[threadIdx.x] = a0; s1[threadIdx.x] = a1;
    __syncthreads();
    for (int st = 128; st; st >>= 1) {
        if (threadIdx.x < st) {
            s0[threadIdx.x] += s0[threadIdx.x + st];
            s1[threadIdx.x] += s1[threadIdx.x + st];
        }
        __syncthreads();
    }
    if (threadIdx.x == 0) { g_aps[blockIdx.x * 2] = s0[0]; g_aps[blockIdx.x * 2 + 1] = s1[0]; }
}

__global__ void asumfin() {
    if (threadIdx.x < 2) {
        int cc = threadIdx.x;
        float s = 0.f;
        for (int b = 0; b < 256; b++) s += g_aps[b * 2 + cc];
        g_asum[cc] = s;
    }
}

__global__ void anorm(float* __restrict__ out, int n) {
    float m0 = g_amax[0], m1 = g_amax[1];
    float r0 = 1.0f / g_asum[0], r1 = 1.0f / g_asum[1];
    for (int i = blockIdx.x * blockDim.x + threadIdx.x; i < n; i += gridDim.x * blockDim.x) {
        out[2 + (size_t)i * 2] = expf(g_Alog[(size_t)i * 2] - m0) * r0;
        out[2 + (size_t)i * 2 + 1] = expf(g_Alog[(size_t)i * 2 + 1] - m1) * r1;
    }
}

// ---------------- B = A^T @ V (deterministic 2-stage) ----------------
__global__ void bpart(const float* __restrict__ out, int n) {
    int b = blockIdx.x;
    int col = threadIdx.x; // 512 threads
    int chunk = (n + gridDim.x - 1) / gridDim.x;
    int r0 = b * chunk;
    int r1 = min(n, r0 + chunk);
    float a0 = 0.f, a1 = 0.f;
    const float* Aout = out + 2;
    for (int r = r0; r < r1; r++) {
        float A0 = Aout[(size_t)r * 2];
        float A1 = Aout[(size_t)r * 2 + 1];
        float v = g_V[(size_t)r * DD + col];
        a0 = fmaf(A0, v, a0);
        a1 = fmaf(A1, v, a1);
    }
    g_Bpart[(b * 2 + 0) * DD + col] = a0;
    g_Bpart[(b * 2 + 1) * DD + col] = a1;
}

__global__ void bfin(float* __restrict__ out, int n) {
    int col = threadIdx.x; // 512 threads
    float a0 = 0.f, a1 = 0.f;
    for (int b = 0; b < BBLK; b++) {
        a0 += g_Bpart[(b * 2 + 0) * DD + col];
        a1 += g_Bpart[(b * 2 + 1) * DD + col];
    }
    g_B[col] = a0;
    g_B[DD + col] = a1;
    size_t off = 2 + (size_t)2 * n;
    out[off + col] = a0;
    out[off + DD + col] = a1;
}

// ---------------- Cout = einsum('id,oid->o', B, W_fcc) + b_fcc ----------------
__global__ void coutk(const float* __restrict__ Wf, const float* __restrict__ bf,
                      float* __restrict__ out) {
    __shared__ float s0[256], s1[256];
    int t = threadIdx.x;
    float a0 = 0.f, a1 = 0.f;
    for (int idx = t; idx < 1024; idx += 256) {
        float b = g_B[idx];
        a0 = fmaf(b, Wf[idx], a0);
        a1 = fmaf(b, Wf[1024 + idx], a1);
    }
    s0[t] = a0; s1[t] = a1;
    __syncthreads();
    for (int st = 128; st; st >>= 1) {
        if (t < st) { s0[t] += s0[t + st]; s1[t] += s1[t + st]; }
        __syncthreads();
    }
    if (t == 0) {
        out[0] = s0[0] + bf[0];
        out[1] = s1[0] + bf[1];
    }
}

// ---------------- launch ----------------
extern "C" void kernel_launch(void* const* d_in, const int* in_sizes, int n_in,
                              void* d_out, int out_size) {
    const float* feats = (const float*)d_in[0];
    const float* c     = (const float*)d_in[1];
    const float* sp    = (const float*)d_in[2];
    const float* Wlin  = (const float*)d_in[3];
    const float* blin  = (const float*)d_in[4];
    const float* Wq    = (const float*)d_in[5];
    const float* bq    = (const float*)d_in[6];
    const float* Wv    = (const float*)d_in[7];
    const float* bv    = (const float*)d_in[8];
    const float* Wf    = (const float*)d_in[9];
    const float* bf    = (const float*)d_in[10];
    float* out = (float*)d_out;

    int n = in_sizes[2];
    int k = (int)(0.2 * (double)n);

    // 1) bottom-k select + zero
    init_sel<<<1, 256>>>(k);
    for (int p = 0; p < 4; p++) {
        hist_kernel<<<256, 256>>>(sp, n, p);
        scan_kernel<<<1, 256>>>(p);
    }
    zero_kernel<<<256, 256>>>(sp, n);

    // 2) instance softmax -> scale
    maxpart<<<256, 256>>>(n);
    maxfin<<<1, 256>>>();
    sumpart<<<256, 256>>>(n);
    sumfin<<<1, 256>>>();
    scalek<<<256, 256>>>(n);

    // 3) f = relu((feats*scale) @ Wlin^T + blin)
    dim3 grid1((n + 127) / 128, DD / 128);
    gemm_kernel<<<grid1, 256>>>(feats, Wlin, blin, n, 0);

    // 4) critical instances and q_max
    cargpart<<<128, 256>>>(c, n);
    cargfin<<<1, 32>>>();
    qmaxk<<<1, 256>>>(Wq, bq);

    // 5) V = f @ Wv^T + bv
    gemm_kernel<<<grid1, 256>>>(feats, Wv, bv, n, 1);

    // 6) A_logits = tanh(f @ Wq^T + bq) @ q_max^T / sqrt(128)   (fused)
    dim3 gridq((n + 127) / 128, 1);
    gemmq_kernel<<<gridq, 256>>>(Wq, bq, n);

    // 7) column softmax of A -> out[2 : 2+2n]
    amaxpart<<<256, 256>>>(n);
    amaxfin<<<1, 32>>>();
    asumpart<<<256, 256>>>(n);
    asumfin<<<1, 32>>>();
    anorm<<<256, 256>>>(out, n);

    // 8) B = A^T @ V -> out[2+2n : 2+2n+1024]
    bpart<<<BBLK, DD>>>(out, n);
    bfin<<<1, DD>>>(out, n);

    // 9) Cout -> out[0:2]
    coutk<<<1, 256>>>(Wf, bf, out);
}